// round 16
// baseline (speedup 1.0000x reference)
#include <cuda_runtime.h>
#include <cuda_bf16.h>
#include <cstdint>

// -----------------------------------------------------------------------------
// OConnorWeatherall belief update, N=500000, K=64, TRIALS=10.
//
// PASSING arithmetic (R9, bit-exact vs GPU-jax/XLA:GPU — FROZEN):
//   pl   = rn(prior*lik)                      // two uses -> NOT fused (NVPTX)
//   marg = fma(1-prior, alt, pl)              // N1-side fusion
//   cert = max(fma(-(delta*mst), 1-marg, 1), 0)
//   post = fma(bel, cert, rn(mis*(1-cert)))
//   div.rn (__fdiv_rn); pow = libdevice __nv_powf.
//
// R15: kernel is L2-concurrency bound (R14: removing 8M nbr wavefronts via TMA
// changed nothing; L2 pinned at 68% = 0.7 sect/cyc/LTS). cp.async record
// gathers into per-thread smem staging decouple outstanding loads from
// registers: depth 16/thread at 4 CTAs/SM -> ~512 in-flight sectors/SM
// (vs ~320) -> push L2 toward saturation. Fallback = R10 kernel (143.9us).
// -----------------------------------------------------------------------------

extern "C" __device__ float __nv_powf(float, float);   // libdevice (XLA:GPU pow)

#define MAXN 500000
#define BLK  256

#define TBL_BYTES   (11 * BLK * 8)          // float2 table: 22528
#define SLOTS       4
#define STAGE_BYTES (SLOTS * 4 * BLK * 8)   // 4 slots x 4 recs x 256 thr x 8B
#define DYN_SMEM    (TBL_BYTES + STAGE_BYTES)  // 55296

__device__ __align__(8) static uint2 g_records[MAXN];

__global__ void pack_kernel(const float* __restrict__ belief,
                            const float2* __restrict__ payoff,
                            int n) {
    int i = blockIdx.x * blockDim.x + threadIdx.x;
    if (i >= n) return;
    float2 st = payoff[i];
    unsigned meta = 0u;
    if (st.y > 0.0f) {
        meta = 0x100u | (unsigned)__float2int_rn(st.x);
    }
    g_records[i] = make_uint2(__float_as_uint(belief[i]), meta);
}

__device__ __forceinline__ uint32_t smem_u32(const void* p) {
    uint32_t a;
    asm("{ .reg .u64 t; cvta.to.shared.u64 t, %1; cvt.u32.u64 %0, t; }"
        : "=r"(a) : "l"(p));
    return a;
}

#define CP_WAIT(N) asm volatile("cp.async.wait_group " #N ";" ::: "memory")

__device__ __forceinline__ void cp8(uint32_t dst, const uint2* src) {
    unsigned long long g = (unsigned long long)__cvta_generic_to_global((void*)src);
    asm volatile("cp.async.ca.shared.global [%0], [%1], 8;"
                 :: "r"(dst), "l"(g) : "memory");
}

// Issue one group: 4 record gathers into staging slot (k-major) + commit.
__device__ __forceinline__ void issue_group(uint32_t slot_dst, int4 j) {
    cp8(slot_dst + 0u,    &g_records[j.x]);
    cp8(slot_dst + 2048u, &g_records[j.y]);
    cp8(slot_dst + 4096u, &g_records[j.z]);
    cp8(slot_dst + 6144u, &g_records[j.w]);
    asm volatile("cp.async.commit_group;" ::: "memory");
}

// One fold step: NVPTX hasOneUse-contracted tree (bit-exact, FROZEN).
__device__ __forceinline__ float fold_step(float prior, uint2 rec,
                                           const float2* __restrict__ T,
                                           float mst) {
    unsigned meta = rec.y;
    if (meta & 0x100u) {
        float b   = __uint_as_float(rec.x);
        int   s   = (int)(meta & 0xFFu);
        float2 la = T[s * BLK];
        float lik = la.x;
        float alt = la.y;
        float delta = fabsf(__fsub_rn(prior, b));
        float pl    = __fmul_rn(prior, lik);
        float marg  = __fmaf_rn(__fsub_rn(1.0f, prior), alt, pl);
        float omm   = __fsub_rn(1.0f, marg);
        float bel   = __fdiv_rn(pl, marg);
        float mis   = __fdiv_rn(__fmul_rn(prior, __fsub_rn(1.0f, lik)), omm);
        float u     = __fmul_rn(delta, mst);
        float cert  = fmaxf(__fmaf_rn(-u, omm, 1.0f), 0.0f);
        prior = __fmaf_rn(bel, cert,
                          __fmul_rn(mis, __fsub_rn(1.0f, cert)));
    }
    return prior;
}

__device__ __forceinline__ void build_table(float p, float2* Tt) {
    float q = __fsub_rn(1.0f, p);
    float L[11];
#pragma unroll
    for (int s = 0; s <= 10; ++s) {
        float ps = __nv_powf(p, (float)s);
        float qf = __nv_powf(q, (float)(10 - s));
        L[s] = __fmul_rn(ps, qf);
    }
#pragma unroll
    for (int s = 0; s <= 10; ++s) {
        Tt[s * BLK] = make_float2(L[s], L[10 - s]);
    }
}

// ---- cp.async-staged fold kernel -------------------------------------------

__global__ __launch_bounds__(BLK)
void fold_async_kernel(const float* __restrict__ belief,
                       const float* __restrict__ prob,
                       const float* __restrict__ mistrust,
                       const int*   __restrict__ nbr,
                       float*       __restrict__ out,
                       int n) {
    extern __shared__ __align__(16) unsigned char dynsmem[];
    float2* Tsh = (float2*)dynsmem;                       // [11][BLK]
    // staging: uint2 [SLOTS][4][BLK], k-major inside a slot

    int tid = threadIdx.x;
    int i = blockIdx.x * BLK + tid;
    bool valid = (i < n);

    float p = valid ? prob[i] : 0.7f;
    build_table(p, Tsh + tid);
    if (!valid) return;      // all machinery below is per-thread: safe to exit

    const float2* Tt = Tsh + tid;
    float prior = belief[i];
    float mst   = mistrust[i];

    const int4* nrow = (const int4*)(nbr + (long long)i * 64);
    uint32_t stage0 = smem_u32(dynsmem + TBL_BYTES) + (uint32_t)tid * 8u;
    const uint2* Sbase = (const uint2*)(dynsmem + TBL_BYTES) + tid;

    // Prologue: fill 4 slots (16 records in flight).
    int4 j0 = __ldcs(nrow + 0);
    int4 j1 = __ldcs(nrow + 1);
    int4 j2 = __ldcs(nrow + 2);
    int4 j3 = __ldcs(nrow + 3);
    issue_group(stage0 + 0u * 8192u, j0);
    issue_group(stage0 + 1u * 8192u, j1);
    issue_group(stage0 + 2u * 8192u, j2);
    issue_group(stage0 + 3u * 8192u, j3);
    int4 np0 = __ldcs(nrow + 4);
    int4 np1 = __ldcs(nrow + 5);

#pragma unroll
    for (int g = 0; g < 16; ++g) {
        if (g <= 12)      CP_WAIT(3);
        else if (g == 13) CP_WAIT(2);
        else if (g == 14) CP_WAIT(1);
        else              CP_WAIT(0);

        int d = g & 3;
        const uint2* S = Sbase + d * (4 * BLK);
        uint2 r0 = S[0 * BLK];
        uint2 r1 = S[1 * BLK];
        uint2 r2 = S[2 * BLK];
        uint2 r3 = S[3 * BLK];

        prior = fold_step(prior, r0, Tt, mst);
        prior = fold_step(prior, r1, Tt, mst);
        prior = fold_step(prior, r2, Tt, mst);
        prior = fold_step(prior, r3, Tt, mst);

        if (g <= 11) {
            int4 jx = np0;
            np0 = np1;
            if (g <= 9) np1 = __ldcs(nrow + g + 6);
            issue_group(stage0 + (uint32_t)d * 8192u, jx);
        }
    }

    out[i] = prior;
}

// ---- R10 fallback fold kernel (best known: 143.9us) -------------------------

__global__ __launch_bounds__(BLK)
void fold_kernel(const float* __restrict__ belief,
                 const float* __restrict__ prob,
                 const float* __restrict__ mistrust,
                 const int*   __restrict__ nbr,
                 float*       __restrict__ out,
                 int n) {
    __shared__ float2 Tsh[11 * BLK];
    int tid = threadIdx.x;
    int i = blockIdx.x * BLK + tid;
    bool valid = (i < n);

    float p = valid ? prob[i] : 0.7f;
    build_table(p, Tsh + tid);
    if (!valid) return;

    const float2* Tt = Tsh + tid;
    float prior = belief[i];
    float mst   = mistrust[i];

    const int4* nrow = (const int4*)(nbr + (long long)i * 64);

    int4 n2 = __ldcs(nrow + 2);
    int4 r01 = __ldcs(nrow + 0);
    int4 r11 = __ldcs(nrow + 1);
    uint2 A0 = __ldg(&g_records[r01.x]);
    uint2 A1 = __ldg(&g_records[r01.y]);
    uint2 A2 = __ldg(&g_records[r01.z]);
    uint2 A3 = __ldg(&g_records[r01.w]);
    uint2 B0 = __ldg(&g_records[r11.x]);
    uint2 B1 = __ldg(&g_records[r11.y]);
    uint2 B2 = __ldg(&g_records[r11.z]);
    uint2 B3 = __ldg(&g_records[r11.w]);

#pragma unroll
    for (int g = 0; g < 16; ++g) {
        uint2 C0, C1, C2, C3;
        int4  nn = n2;
        if (g <= 13) {
            C0 = __ldg(&g_records[n2.x]);
            C1 = __ldg(&g_records[n2.y]);
            C2 = __ldg(&g_records[n2.z]);
            C3 = __ldg(&g_records[n2.w]);
        }
        if (g <= 12) nn = __ldcs(nrow + g + 3);

        prior = fold_step(prior, A0, Tt, mst);
        prior = fold_step(prior, A1, Tt, mst);
        prior = fold_step(prior, A2, Tt, mst);
        prior = fold_step(prior, A3, Tt, mst);

        if (g <= 13) {
            A0 = B0; A1 = B1; A2 = B2; A3 = B3;
            B0 = C0; B1 = C1; B2 = C2; B3 = C3;
        } else {
            A0 = B0; A1 = B1; A2 = B2; A3 = B3;
        }
        n2 = nn;
    }

    out[i] = prior;
}

// ---- generic fallback (unexpected shapes) -----------------------------------

__global__ void fold_generic_kernel(const float* __restrict__ belief,
                                    const float* __restrict__ prob,
                                    const float* __restrict__ mistrust,
                                    const float* __restrict__ payoff,
                                    const int*   __restrict__ nbr,
                                    float*       __restrict__ out,
                                    int n, int K) {
    int i = blockIdx.x * blockDim.x + threadIdx.x;
    if (i >= n) return;
    float p = prob[i];
    float q = __fsub_rn(1.0f, p);
    float mst = mistrust[i];
    float prior = belief[i];
    for (int k = 0; k < K; ++k) {
        int j = nbr[(long long)i * K + k];
        float t = payoff[2 * j + 1];
        if (t > 0.0f) {
            float s = payoff[2 * j];
            float f = __fsub_rn(t, s);
            float b = belief[j];
            float lik = __fmul_rn(__nv_powf(p, s), __nv_powf(q, f));
            float alt = __fmul_rn(__nv_powf(q, s), __nv_powf(p, f));
            float delta = fabsf(__fsub_rn(prior, b));
            float pl    = __fmul_rn(prior, lik);
            float marg  = __fmaf_rn(__fsub_rn(1.0f, prior), alt, pl);
            float omm   = __fsub_rn(1.0f, marg);
            float bel   = __fdiv_rn(pl, marg);
            float mis   = __fdiv_rn(__fmul_rn(prior, __fsub_rn(1.0f, lik)), omm);
            float u     = __fmul_rn(delta, mst);
            float cert  = fmaxf(__fmaf_rn(-u, omm, 1.0f), 0.0f);
            prior = __fmaf_rn(bel, cert,
                              __fmul_rn(mis, __fsub_rn(1.0f, cert)));
        }
    }
    out[i] = prior;
}

// ---- host -------------------------------------------------------------------

extern "C" void kernel_launch(void* const* d_in, const int* in_sizes, int n_in,
                              void* d_out, int out_size) {
    const float* belief   = (const float*)d_in[0];
    const float* prob     = (const float*)d_in[1];
    const float* mistrust = (const float*)d_in[2];
    const float* payoff   = (const float*)d_in[3];
    const int*   nbr      = (const int*)d_in[4];
    float*       out      = (float*)d_out;

    int n = in_sizes[0];
    int K = (n > 0) ? (in_sizes[4] / n) : 0;
    int grid = (n + BLK - 1) / BLK;

    if (K == 64 && n <= MAXN && n > 0) {
        pack_kernel<<<grid, BLK>>>(belief, (const float2*)payoff, n);

        static int async_ok = -1;   // one-time attribute setup (deterministic)
        if (async_ok < 0) {
            cudaError_t e = cudaFuncSetAttribute(
                fold_async_kernel,
                cudaFuncAttributeMaxDynamicSharedMemorySize, DYN_SMEM);
            async_ok = (e == cudaSuccess) ? 1 : 0;
        }
        if (async_ok == 1) {
            fold_async_kernel<<<grid, BLK, DYN_SMEM>>>(belief, prob, mistrust,
                                                       nbr, out, n);
        } else {
            fold_kernel<<<grid, BLK>>>(belief, prob, mistrust, nbr, out, n);
        }
    } else {
        fold_generic_kernel<<<grid, BLK>>>(belief, prob, mistrust, payoff, nbr,
                                           out, n, K);
    }
}

// round 17
// speedup vs baseline: 1.8688x; 1.8688x over previous
#include <cuda_runtime.h>
#include <cuda_bf16.h>
#include <cstdint>

// -----------------------------------------------------------------------------
// OConnorWeatherall belief update, N=500000, K=64, TRIALS=10.
//
// PASSING arithmetic (R9, bit-exact vs GPU-jax/XLA:GPU — FROZEN):
//   pl   = rn(prior*lik)                      // two uses -> NOT fused (NVPTX)
//   marg = fma(1-prior, alt, pl)              // N1-side fusion
//   cert = max(fma(-(delta*mst), 1-marg, 1), 0)
//   post = fma(bel, cert, rn(mis*(1-cert)))
//   div.rn (__fdiv_rn); pow = libdevice __nv_powf.
//
// R16: persistent-CTA tail fix. grid=1954 over 740 resident slots = 2.64
// waves quantized to 3 (12% idle tail). Launch exactly 740 CTAs; each owns a
// contiguous ~676-node range processed in 256-node chunks with the R10 body
// (depth-8 register pipeline — best measured 143.9us). Imbalance drops from
// 0.36*T_CTA to ~one warp-chunk. __launch_bounds__(256,5) pins 5 CTAs/SM.
// R15 lesson: cp.async 8B gathers = 8cyc/op issue floor, never again.
// -----------------------------------------------------------------------------

extern "C" __device__ float __nv_powf(float, float);   // libdevice (XLA:GPU pow)

#define MAXN 500000
#define BLK  256
#define NSLOTS (148 * 5)

__device__ __align__(8) static uint2 g_records[MAXN];

__global__ void pack_kernel(const float* __restrict__ belief,
                            const float2* __restrict__ payoff,
                            int n) {
    int i = blockIdx.x * blockDim.x + threadIdx.x;
    if (i >= n) return;
    float2 st = payoff[i];
    unsigned meta = 0u;
    if (st.y > 0.0f) {
        meta = 0x100u | (unsigned)__float2int_rn(st.x);
    }
    g_records[i] = make_uint2(__float_as_uint(belief[i]), meta);
}

// One fold step: NVPTX hasOneUse-contracted tree (bit-exact, FROZEN).
// T = thread's private float2 smem column, stride BLK: T[s] = (lik_s, alt_s).
__device__ __forceinline__ float fold_step(float prior, uint2 rec,
                                           const float2* __restrict__ T,
                                           float mst) {
    unsigned meta = rec.y;
    if (meta & 0x100u) {
        float b   = __uint_as_float(rec.x);
        int   s   = (int)(meta & 0xFFu);
        float2 la = T[s * BLK];
        float lik = la.x;
        float alt = la.y;
        float delta = fabsf(__fsub_rn(prior, b));
        float pl    = __fmul_rn(prior, lik);
        float marg  = __fmaf_rn(__fsub_rn(1.0f, prior), alt, pl);
        float omm   = __fsub_rn(1.0f, marg);
        float bel   = __fdiv_rn(pl, marg);
        float mis   = __fdiv_rn(__fmul_rn(prior, __fsub_rn(1.0f, lik)), omm);
        float u     = __fmul_rn(delta, mst);
        float cert  = fmaxf(__fmaf_rn(-u, omm, 1.0f), 0.0f);
        prior = __fmaf_rn(bel, cert,
                          __fmul_rn(mis, __fsub_rn(1.0f, cert)));
    }
    return prior;
}

__device__ __forceinline__ void build_table(float p, float2* Tt) {
    float q = __fsub_rn(1.0f, p);
    float L[11];
#pragma unroll
    for (int s = 0; s <= 10; ++s) {
        float ps = __nv_powf(p, (float)s);
        float qf = __nv_powf(q, (float)(10 - s));
        L[s] = __fmul_rn(ps, qf);
    }
#pragma unroll
    for (int s = 0; s <= 10; ++s) {
        Tt[s * BLK] = make_float2(L[s], L[10 - s]);
    }
}

// Fold one 256-node chunk starting at node0 (R10 body, unchanged).
__device__ __forceinline__ void fold_chunk(int node0, int n,
                                           const float* __restrict__ belief,
                                           const float* __restrict__ prob,
                                           const float* __restrict__ mistrust,
                                           const int*   __restrict__ nbr,
                                           float*       __restrict__ out,
                                           float2* Tsh) {
    int tid = threadIdx.x;
    int i = node0 + tid;
    if (i >= n) return;          // per-thread only, no syncs anywhere

    build_table(prob[i], Tsh + tid);
    const float2* Tt = Tsh + tid;
    float prior = belief[i];
    float mst   = mistrust[i];

    const int4* nrow = (const int4*)(nbr + (long long)i * 64);

    // Depth-8 pipeline: groups A (resident), B (arriving), C issued this iter.
    int4 n2 = __ldcs(nrow + 2);
    int4 r01 = __ldcs(nrow + 0);
    int4 r11 = __ldcs(nrow + 1);
    uint2 A0 = __ldg(&g_records[r01.x]);
    uint2 A1 = __ldg(&g_records[r01.y]);
    uint2 A2 = __ldg(&g_records[r01.z]);
    uint2 A3 = __ldg(&g_records[r01.w]);
    uint2 B0 = __ldg(&g_records[r11.x]);
    uint2 B1 = __ldg(&g_records[r11.y]);
    uint2 B2 = __ldg(&g_records[r11.z]);
    uint2 B3 = __ldg(&g_records[r11.w]);

#pragma unroll
    for (int g = 0; g < 16; ++g) {
        uint2 C0, C1, C2, C3;
        int4  nn = n2;
        if (g <= 13) {
            C0 = __ldg(&g_records[n2.x]);
            C1 = __ldg(&g_records[n2.y]);
            C2 = __ldg(&g_records[n2.z]);
            C3 = __ldg(&g_records[n2.w]);
        }
        if (g <= 12) nn = __ldcs(nrow + g + 3);

        prior = fold_step(prior, A0, Tt, mst);
        prior = fold_step(prior, A1, Tt, mst);
        prior = fold_step(prior, A2, Tt, mst);
        prior = fold_step(prior, A3, Tt, mst);

        if (g <= 13) {
            A0 = B0; A1 = B1; A2 = B2; A3 = B3;
            B0 = C0; B1 = C1; B2 = C2; B3 = C3;
        } else {
            A0 = B0; A1 = B1; A2 = B2; A3 = B3;
        }
        n2 = nn;
    }

    out[i] = prior;
}

// Persistent fold: each CTA owns a contiguous node range in 256-node chunks.
__global__ __launch_bounds__(BLK, 5)
void fold_persist_kernel(const float* __restrict__ belief,
                         const float* __restrict__ prob,
                         const float* __restrict__ mistrust,
                         const int*   __restrict__ nbr,
                         float*       __restrict__ out,
                         int n, int per_cta) {
    __shared__ float2 Tsh[11 * BLK];
    int base = blockIdx.x * per_cta;
    int end  = base + per_cta;
    if (end > n) end = n;
    for (int node0 = base; node0 < end; node0 += BLK) {
        fold_chunk(node0, (node0 + BLK <= end) ? (node0 + BLK) : end,
                   belief, prob, mistrust, nbr, out, Tsh);
    }
}

// ---- generic fallback (unexpected shapes) -----------------------------------

__global__ void fold_generic_kernel(const float* __restrict__ belief,
                                    const float* __restrict__ prob,
                                    const float* __restrict__ mistrust,
                                    const float* __restrict__ payoff,
                                    const int*   __restrict__ nbr,
                                    float*       __restrict__ out,
                                    int n, int K) {
    int i = blockIdx.x * blockDim.x + threadIdx.x;
    if (i >= n) return;
    float p = prob[i];
    float q = __fsub_rn(1.0f, p);
    float mst = mistrust[i];
    float prior = belief[i];
    for (int k = 0; k < K; ++k) {
        int j = nbr[(long long)i * K + k];
        float t = payoff[2 * j + 1];
        if (t > 0.0f) {
            float s = payoff[2 * j];
            float f = __fsub_rn(t, s);
            float b = belief[j];
            float lik = __fmul_rn(__nv_powf(p, s), __nv_powf(q, f));
            float alt = __fmul_rn(__nv_powf(q, s), __nv_powf(p, f));
            float delta = fabsf(__fsub_rn(prior, b));
            float pl    = __fmul_rn(prior, lik);
            float marg  = __fmaf_rn(__fsub_rn(1.0f, prior), alt, pl);
            float omm   = __fsub_rn(1.0f, marg);
            float bel   = __fdiv_rn(pl, marg);
            float mis   = __fdiv_rn(__fmul_rn(prior, __fsub_rn(1.0f, lik)), omm);
            float u     = __fmul_rn(delta, mst);
            float cert  = fmaxf(__fmaf_rn(-u, omm, 1.0f), 0.0f);
            prior = __fmaf_rn(bel, cert,
                              __fmul_rn(mis, __fsub_rn(1.0f, cert)));
        }
    }
    out[i] = prior;
}

// ---- host -------------------------------------------------------------------

extern "C" void kernel_launch(void* const* d_in, const int* in_sizes, int n_in,
                              void* d_out, int out_size) {
    const float* belief   = (const float*)d_in[0];
    const float* prob     = (const float*)d_in[1];
    const float* mistrust = (const float*)d_in[2];
    const float* payoff   = (const float*)d_in[3];
    const int*   nbr      = (const int*)d_in[4];
    float*       out      = (float*)d_out;

    int n = in_sizes[0];
    int K = (n > 0) ? (in_sizes[4] / n) : 0;

    if (K == 64 && n <= MAXN && n > 0) {
        int grid_pack = (n + BLK - 1) / BLK;
        pack_kernel<<<grid_pack, BLK>>>(belief, (const float2*)payoff, n);

        int slots = NSLOTS;
        int ntiles = (n + BLK - 1) / BLK;
        int grid = (ntiles < slots) ? ntiles : slots;
        // Contiguous per-CTA range, multiple of nothing required; chunked by BLK.
        int per_cta = (n + grid - 1) / grid;
        fold_persist_kernel<<<grid, BLK>>>(belief, prob, mistrust, nbr, out,
                                           n, per_cta);
    } else {
        int grid = (n + BLK - 1) / BLK;
        fold_generic_kernel<<<grid, BLK>>>(belief, prob, mistrust, payoff, nbr,
                                           out, n, K);
    }
}